// round 1
// baseline (speedup 1.0000x reference)
#include <cuda_runtime.h>
#include <math.h>

#define N_NODES 50000
#define N_EDGES 1600000
#define E_TOT   (N_EDGES + N_NODES)
#define HID     128
#define SLOPE   0.2f

// ------------------------- device scratch (no allocs allowed) ---------------
__device__ float g_XL[(size_t)N_NODES * HID];
__device__ float g_XR[(size_t)N_NODES * HID];
__device__ float g_H1[(size_t)N_NODES * HID];
__device__ int   g_DEG[N_NODES];
__device__ int   g_ROWPTR[N_NODES + 1];
__device__ int   g_CURSOR[N_NODES];
__device__ int   g_CSR[E_TOT];
__device__ int   g_PART[64];
__device__ int   g_is64;

// ------------------------- edge dtype detection ------------------------------
// If edge_index is int64 (little-endian), every odd 32-bit word is a high half
// of a value in [0, 50000) -> zero. If int32, odd words are random node ids.
__global__ void k_detect(const int* __restrict__ e) {
    __shared__ int s;
    if (threadIdx.x == 0) s = 0;
    __syncthreads();
    if (e[2 * threadIdx.x + 1] != 0) atomicOr(&s, 1);
    __syncthreads();
    if (threadIdx.x == 0) g_is64 = (s == 0) ? 1 : 0;
}

__device__ __forceinline__ int edge_val(const void* e, int is64, int idx) {
    return is64 ? (int)((const long long*)e)[idx] : ((const int*)e)[idx];
}

// ------------------------- CSR build -----------------------------------------
__global__ void k_zero_deg() {
    int i = blockIdx.x * blockDim.x + threadIdx.x;
    if (i < N_NODES) g_DEG[i] = 0;
}

__global__ void k_hist(const void* __restrict__ e) {
    int i = blockIdx.x * blockDim.x + threadIdx.x;
    if (i >= E_TOT) return;
    int is64 = g_is64;
    int d = (i < N_EDGES) ? edge_val(e, is64, N_EDGES + i) : (i - N_EDGES);
    atomicAdd(&g_DEG[d], 1);
}

__global__ void k_scan1() {
    __shared__ int s[1024];
    int i = blockIdx.x * 1024 + threadIdx.x;
    int v = (i < N_NODES) ? g_DEG[i] : 0;
    s[threadIdx.x] = v;
    __syncthreads();
    #pragma unroll
    for (int off = 1; off < 1024; off <<= 1) {
        int t = (threadIdx.x >= off) ? s[threadIdx.x - off] : 0;
        __syncthreads();
        s[threadIdx.x] += t;
        __syncthreads();
    }
    if (i < N_NODES) g_ROWPTR[i] = s[threadIdx.x] - v;  // block-local exclusive
    if (threadIdx.x == 1023) g_PART[blockIdx.x] = s[1023];
}

__global__ void k_scan2(int nblk) {
    if (threadIdx.x == 0) {
        int run = 0;
        for (int b = 0; b < nblk; b++) { int t = g_PART[b]; g_PART[b] = run; run += t; }
    }
}

__global__ void k_scan3() {
    int i = blockIdx.x * 1024 + threadIdx.x;
    if (i < N_NODES) {
        int r = g_ROWPTR[i] + g_PART[blockIdx.x];
        g_ROWPTR[i] = r;
        g_CURSOR[i] = r;
    }
    if (i == 0) g_ROWPTR[N_NODES] = E_TOT;
}

__global__ void k_scatter(const void* __restrict__ e) {
    int i = blockIdx.x * blockDim.x + threadIdx.x;
    if (i >= E_TOT) return;
    int is64 = g_is64;
    int s_, d_;
    if (i < N_EDGES) {
        s_ = edge_val(e, is64, i);
        d_ = edge_val(e, is64, N_EDGES + i);
    } else {
        s_ = d_ = i - N_EDGES;
    }
    int pos = atomicAdd(&g_CURSOR[d_], 1);
    g_CSR[pos] = s_;
}

// ------------------------- SGEMM: C[M,128] = A[M,128] @ W[128,128] -----------
#define BM 128
#define BN 128
#define BK 16

__global__ __launch_bounds__(256) void k_gemm(const float* __restrict__ A,
                                              const float* __restrict__ W,
                                              float* __restrict__ C, int M) {
    __shared__ float As[BM][BK + 1];
    __shared__ float Bs[BK][BN];
    int tid = threadIdx.x;
    int ty = tid >> 4;   // 0..15, row group
    int tx = tid & 15;   // 0..15, col group
    int m0 = blockIdx.x * BM;

    float acc[8][8];
    #pragma unroll
    for (int i = 0; i < 8; i++)
        #pragma unroll
        for (int j = 0; j < 8; j++) acc[i][j] = 0.f;

    for (int k0 = 0; k0 < 128; k0 += BK) {
        // load A tile (128x16 = 512 float4, 2 per thread)
        #pragma unroll
        for (int j = 0; j < 2; j++) {
            int f = tid * 2 + j;
            int r = f >> 2, c4 = f & 3;
            float4 v = make_float4(0.f, 0.f, 0.f, 0.f);
            if (m0 + r < M)
                v = *(const float4*)(A + (size_t)(m0 + r) * 128 + k0 + c4 * 4);
            As[r][c4 * 4 + 0] = v.x; As[r][c4 * 4 + 1] = v.y;
            As[r][c4 * 4 + 2] = v.z; As[r][c4 * 4 + 3] = v.w;
        }
        // load W tile (16x128 = 512 float4, 2 per thread)
        #pragma unroll
        for (int j = 0; j < 2; j++) {
            int f = tid * 2 + j;
            int r = f >> 5, c4 = f & 31;
            float4 v = *(const float4*)(W + (size_t)(k0 + r) * 128 + c4 * 4);
            *(float4*)&Bs[r][c4 * 4] = v;
        }
        __syncthreads();

        #pragma unroll
        for (int k = 0; k < BK; k++) {
            float a[8], b[8];
            #pragma unroll
            for (int i = 0; i < 4; i++) {
                a[i]     = As[ty * 4 + i][k];
                a[4 + i] = As[64 + ty * 4 + i][k];
            }
            float4 b0 = *(float4*)&Bs[k][tx * 4];
            float4 b1 = *(float4*)&Bs[k][64 + tx * 4];
            b[0] = b0.x; b[1] = b0.y; b[2] = b0.z; b[3] = b0.w;
            b[4] = b1.x; b[5] = b1.y; b[6] = b1.z; b[7] = b1.w;
            #pragma unroll
            for (int i = 0; i < 8; i++)
                #pragma unroll
                for (int j = 0; j < 8; j++) acc[i][j] += a[i] * b[j];
        }
        __syncthreads();
    }

    #pragma unroll
    for (int i = 0; i < 8; i++) {
        int r = m0 + ((i < 4) ? (ty * 4 + i) : (64 + ty * 4 + (i - 4)));
        if (r < M) {
            float4 v0 = make_float4(acc[i][0], acc[i][1], acc[i][2], acc[i][3]);
            float4 v1 = make_float4(acc[i][4], acc[i][5], acc[i][6], acc[i][7]);
            *(float4*)(C + (size_t)r * 128 + tx * 4)      = v0;
            *(float4*)(C + (size_t)r * 128 + 64 + tx * 4) = v1;
        }
    }
}

// ------------------------- GATv2 aggregation (warp per dst node) -------------
// Online (flash-style) softmax over incoming edges. Lane l holds channels
// [4l, 4l+4); head h = l/8 (C=32 -> 8 lanes per head). Per-head attention dot
// reduced with butterfly shuffles over the 8-lane group.
__global__ __launch_bounds__(256) void k_agg(const float* __restrict__ XL,
                                             const float* __restrict__ XR,
                                             const float* __restrict__ att,
                                             const float* __restrict__ bias,
                                             float* __restrict__ out) {
    int warp = (blockIdx.x * blockDim.x + threadIdx.x) >> 5;
    int lane = threadIdx.x & 31;
    if (warp >= N_NODES) return;

    float4 a4 = __ldg((const float4*)att + lane);
    float4 xr = __ldg((const float4*)(XR + (size_t)warp * 128) + lane);
    int e0 = g_ROWPTR[warp];
    int e1 = g_ROWPTR[warp + 1];

    float m = -1e30f, s = 0.f;
    float4 acc = make_float4(0.f, 0.f, 0.f, 0.f);

    for (int e = e0; e < e1; e++) {
        int src = g_CSR[e];
        float4 xs = __ldg((const float4*)(XL + (size_t)src * 128) + lane);
        float4 mg = make_float4(xs.x + xr.x, xs.y + xr.y, xs.z + xr.z, xs.w + xr.w);
        // leaky_relu(v) == max(v, SLOPE*v) for SLOPE in (0,1)
        float lx = fmaxf(mg.x, SLOPE * mg.x);
        float ly = fmaxf(mg.y, SLOPE * mg.y);
        float lz = fmaxf(mg.z, SLOPE * mg.z);
        float lw = fmaxf(mg.w, SLOPE * mg.w);
        float p = lx * a4.x + ly * a4.y + lz * a4.z + lw * a4.w;
        p += __shfl_xor_sync(0xFFFFFFFFu, p, 1);
        p += __shfl_xor_sync(0xFFFFFFFFu, p, 2);
        p += __shfl_xor_sync(0xFFFFFFFFu, p, 4);

        float mn = fmaxf(m, p);
        float c  = __expf(m - mn);
        float w  = __expf(p - mn);
        s = s * c + w;
        acc.x = acc.x * c + w * xs.x;
        acc.y = acc.y * c + w * xs.y;
        acc.z = acc.z * c + w * xs.z;
        acc.w = acc.w * c + w * xs.w;
        m = mn;
    }

    float inv = 1.f / (s + 1e-16f);
    float4 b4 = __ldg((const float4*)bias + lane);
    float4 o;
    o.x = fmaxf(acc.x * inv + b4.x, 0.f);
    o.y = fmaxf(acc.y * inv + b4.y, 0.f);
    o.z = fmaxf(acc.z * inv + b4.z, 0.f);
    o.w = fmaxf(acc.w * inv + b4.w, 0.f);
    *((float4*)(out + (size_t)warp * 128) + lane) = o;
}

// ------------------------- launch --------------------------------------------
extern "C" void kernel_launch(void* const* d_in, const int* in_sizes, int n_in,
                              void* d_out, int out_size) {
    const float* x    = (const float*)d_in[0];
    const void*  ei   = d_in[1];
    const float* W1l  = (const float*)d_in[2];
    const float* W1r  = (const float*)d_in[3];
    const float* att1 = (const float*)d_in[4];
    const float* b1   = (const float*)d_in[5];
    const float* W2l  = (const float*)d_in[6];
    const float* W2r  = (const float*)d_in[7];
    const float* att2 = (const float*)d_in[8];
    const float* b2   = (const float*)d_in[9];
    float* out = (float*)d_out;

    float *XL, *XR, *H1;
    cudaGetSymbolAddress((void**)&XL, g_XL);
    cudaGetSymbolAddress((void**)&XR, g_XR);
    cudaGetSymbolAddress((void**)&H1, g_H1);

    // CSR build (recomputed every launch; deterministic work)
    k_detect<<<1, 256>>>((const int*)ei);
    k_zero_deg<<<(N_NODES + 255) / 256, 256>>>();
    k_hist<<<(E_TOT + 255) / 256, 256>>>(ei);
    int nblk = (N_NODES + 1023) / 1024;
    k_scan1<<<nblk, 1024>>>();
    k_scan2<<<1, 32>>>(nblk);
    k_scan3<<<nblk, 1024>>>();
    k_scatter<<<(E_TOT + 255) / 256, 256>>>(ei);

    int gemm_grid = (N_NODES + BM - 1) / BM;
    int agg_grid  = (N_NODES * 32 + 255) / 256;

    // layer 1
    k_gemm<<<gemm_grid, 256>>>(x, W1l, XL, N_NODES);
    k_gemm<<<gemm_grid, 256>>>(x, W1r, XR, N_NODES);
    k_agg<<<agg_grid, 256>>>(XL, XR, att1, b1, H1);

    // layer 2
    k_gemm<<<gemm_grid, 256>>>(H1, W2l, XL, N_NODES);
    k_gemm<<<gemm_grid, 256>>>(H1, W2r, XR, N_NODES);
    k_agg<<<agg_grid, 256>>>(XL, XR, att2, b2, out);
}

// round 2
// speedup vs baseline: 1.6877x; 1.6877x over previous
#include <cuda_runtime.h>
#include <math.h>
#include <stdint.h>

#define N_NODES 50000
#define N_EDGES 1600000
#define E_TOT   (N_EDGES + N_NODES)
#define HID     128
#define SLOPE   0.2f

// ------------------------- device scratch (no allocs allowed) ---------------
__device__ float g_XL[(size_t)N_NODES * HID];
__device__ float g_XR[(size_t)N_NODES * HID];
__device__ float g_H1[(size_t)N_NODES * HID];
__device__ int   g_DEG[N_NODES];
__device__ int   g_ROWPTR[N_NODES + 1];
__device__ int   g_CURSOR[N_NODES];
__device__ int   g_CSR[E_TOT];
__device__ int   g_PART[64];
__device__ int   g_is64;

// ------------------------- edge dtype detection ------------------------------
__global__ void k_detect(const int* __restrict__ e) {
    __shared__ int s;
    if (threadIdx.x == 0) s = 0;
    __syncthreads();
    if (e[2 * threadIdx.x + 1] != 0) atomicOr(&s, 1);
    __syncthreads();
    if (threadIdx.x == 0) g_is64 = (s == 0) ? 1 : 0;
}

__device__ __forceinline__ int edge_val(const void* e, int is64, int idx) {
    return is64 ? (int)((const long long*)e)[idx] : ((const int*)e)[idx];
}

// ------------------------- CSR build -----------------------------------------
__global__ void k_zero_deg() {
    int i = blockIdx.x * blockDim.x + threadIdx.x;
    if (i < N_NODES) g_DEG[i] = 0;
}

__global__ void k_hist(const void* __restrict__ e) {
    int i = blockIdx.x * blockDim.x + threadIdx.x;
    if (i >= E_TOT) return;
    int is64 = g_is64;
    int d = (i < N_EDGES) ? edge_val(e, is64, N_EDGES + i) : (i - N_EDGES);
    atomicAdd(&g_DEG[d], 1);
}

__global__ void k_scan1() {
    __shared__ int s[1024];
    int i = blockIdx.x * 1024 + threadIdx.x;
    int v = (i < N_NODES) ? g_DEG[i] : 0;
    s[threadIdx.x] = v;
    __syncthreads();
    #pragma unroll
    for (int off = 1; off < 1024; off <<= 1) {
        int t = (threadIdx.x >= off) ? s[threadIdx.x - off] : 0;
        __syncthreads();
        s[threadIdx.x] += t;
        __syncthreads();
    }
    if (i < N_NODES) g_ROWPTR[i] = s[threadIdx.x] - v;
    if (threadIdx.x == 1023) g_PART[blockIdx.x] = s[1023];
}

__global__ void k_scan2(int nblk) {
    if (threadIdx.x == 0) {
        int run = 0;
        for (int b = 0; b < nblk; b++) { int t = g_PART[b]; g_PART[b] = run; run += t; }
    }
}

__global__ void k_scan3() {
    int i = blockIdx.x * 1024 + threadIdx.x;
    if (i < N_NODES) {
        int r = g_ROWPTR[i] + g_PART[blockIdx.x];
        g_ROWPTR[i] = r;
        g_CURSOR[i] = r;
    }
    if (i == 0) g_ROWPTR[N_NODES] = E_TOT;
}

__global__ void k_scatter(const void* __restrict__ e) {
    int i = blockIdx.x * blockDim.x + threadIdx.x;
    if (i >= E_TOT) return;
    int is64 = g_is64;
    int s_, d_;
    if (i < N_EDGES) {
        s_ = edge_val(e, is64, i);
        d_ = edge_val(e, is64, N_EDGES + i);
    } else {
        s_ = d_ = i - N_EDGES;
    }
    int pos = atomicAdd(&g_CURSOR[d_], 1);
    g_CSR[pos] = s_;
}

// ------------------------- tf32 tensor-core dual GEMM ------------------------
// Computes XL = A @ Wl  and  XR = A @ Wr as one [M x 256] GEMM.
// Block tile 128x256, 512 threads (16 warps in 4M x 4N), warp tile 32x64.
// mma.sync.aligned.m16n8k8.row.col.f32.tf32.tf32.f32
#define AS_STRIDE 36    // 36 % 32 == 4  -> A frag banks 4g+t : conflict-free
#define WS_STRIDE 264   // 264 % 32 == 8 -> B frag banks 8t+g : conflict-free
#define GEMM_SMEM_BYTES ((128 * AS_STRIDE + 32 * WS_STRIDE) * 4)

__device__ __forceinline__ unsigned f2tf32(float x) {
    unsigned u;
    asm("cvt.rna.tf32.f32 %0, %1;" : "=r"(u) : "f"(x));
    return u;
}

__device__ __forceinline__ void mma_tf32(float4& d, const unsigned a[4], const unsigned b[2]) {
    asm volatile(
        "mma.sync.aligned.m16n8k8.row.col.f32.tf32.tf32.f32 "
        "{%0,%1,%2,%3}, {%4,%5,%6,%7}, {%8,%9}, {%0,%1,%2,%3};"
        : "+f"(d.x), "+f"(d.y), "+f"(d.z), "+f"(d.w)
        : "r"(a[0]), "r"(a[1]), "r"(a[2]), "r"(a[3]), "r"(b[0]), "r"(b[1]));
}

__global__ __launch_bounds__(512, 1) void k_gemm_tc(const float* __restrict__ A,
                                                    const float* __restrict__ Wl,
                                                    const float* __restrict__ Wr,
                                                    float* __restrict__ XL,
                                                    float* __restrict__ XR, int M) {
    extern __shared__ float sm[];
    float (*As)[AS_STRIDE] = (float(*)[AS_STRIDE])sm;
    float (*Ws)[WS_STRIDE] = (float(*)[WS_STRIDE])(sm + 128 * AS_STRIDE);

    int tid = threadIdx.x;
    int wid = tid >> 5, lane = tid & 31;
    int g = lane >> 2, t = lane & 3;
    int wm = wid & 3, wn = wid >> 2;
    int m0 = blockIdx.x * 128;

    float4 C[2][8];
    #pragma unroll
    for (int i = 0; i < 2; i++)
        #pragma unroll
        for (int j = 0; j < 8; j++) C[i][j] = make_float4(0.f, 0.f, 0.f, 0.f);

    for (int k0 = 0; k0 < 128; k0 += 32) {
        // A chunk: 128 rows x 32 cols = 1024 float4, 2 per thread
        #pragma unroll
        for (int j = 0; j < 2; j++) {
            int f = tid + 512 * j;
            int row = f >> 3, col = (f & 7) * 4;
            float4 v = make_float4(0.f, 0.f, 0.f, 0.f);
            if (m0 + row < M)
                v = *(const float4*)(A + (size_t)(m0 + row) * 128 + k0 + col);
            As[row][col + 0] = __uint_as_float(f2tf32(v.x));
            As[row][col + 1] = __uint_as_float(f2tf32(v.y));
            As[row][col + 2] = __uint_as_float(f2tf32(v.z));
            As[row][col + 3] = __uint_as_float(f2tf32(v.w));
        }
        // W chunk: 32 rows x 256 cols = 2048 float4, 4 per thread
        #pragma unroll
        for (int j = 0; j < 4; j++) {
            int f = tid + 512 * j;
            int row = f >> 6, col = (f & 63) * 4;
            const float* Wp = (col < 128) ? (Wl + (size_t)(k0 + row) * 128 + col)
                                          : (Wr + (size_t)(k0 + row) * 128 + (col - 128));
            float4 v = *(const float4*)Wp;
            Ws[row][col + 0] = __uint_as_float(f2tf32(v.x));
            Ws[row][col + 1] = __uint_as_float(f2tf32(v.y));
            Ws[row][col + 2] = __uint_as_float(f2tf32(v.z));
            Ws[row][col + 3] = __uint_as_float(f2tf32(v.w));
        }
        __syncthreads();

        #pragma unroll
        for (int ks = 0; ks < 32; ks += 8) {
            unsigned a[2][4], b[8][2];
            #pragma unroll
            for (int mt = 0; mt < 2; mt++) {
                int r = wm * 32 + mt * 16;
                a[mt][0] = __float_as_uint(As[r + g][ks + t]);
                a[mt][1] = __float_as_uint(As[r + g + 8][ks + t]);
                a[mt][2] = __float_as_uint(As[r + g][ks + t + 4]);
                a[mt][3] = __float_as_uint(As[r + g + 8][ks + t + 4]);
            }
            #pragma unroll
            for (int j = 0; j < 8; j++) {
                int n = wn * 64 + j * 8 + g;
                b[j][0] = __float_as_uint(Ws[ks + t][n]);
                b[j][1] = __float_as_uint(Ws[ks + t + 4][n]);
            }
            #pragma unroll
            for (int mt = 0; mt < 2; mt++)
                #pragma unroll
                for (int j = 0; j < 8; j++) mma_tf32(C[mt][j], a[mt], b[j]);
        }
        __syncthreads();
    }

    // epilogue: wn 0,1 -> XL cols 0-127 ; wn 2,3 -> XR cols 0-127
    float* base = (wn < 2) ? XL : XR;
    int ncol0 = (wn & 1) * 64;
    #pragma unroll
    for (int mt = 0; mt < 2; mt++) {
        int r0 = m0 + wm * 32 + mt * 16 + g;
        #pragma unroll
        for (int j = 0; j < 8; j++) {
            int c = ncol0 + j * 8 + 2 * t;
            if (r0 < M)
                *(float2*)(base + (size_t)r0 * 128 + c) = make_float2(C[mt][j].x, C[mt][j].y);
            if (r0 + 8 < M)
                *(float2*)(base + (size_t)(r0 + 8) * 128 + c) = make_float2(C[mt][j].z, C[mt][j].w);
        }
    }
}

// ------------------------- GATv2 aggregation (warp per dst, unroll x4) -------
__device__ __forceinline__ float edge_logit(const float4& xs, const float4& xr,
                                            const float4& a4) {
    float4 mg = make_float4(xs.x + xr.x, xs.y + xr.y, xs.z + xr.z, xs.w + xr.w);
    float lx = fmaxf(mg.x, SLOPE * mg.x);
    float ly = fmaxf(mg.y, SLOPE * mg.y);
    float lz = fmaxf(mg.z, SLOPE * mg.z);
    float lw = fmaxf(mg.w, SLOPE * mg.w);
    return lx * a4.x + ly * a4.y + lz * a4.z + lw * a4.w;
}

__device__ __forceinline__ float head_reduce(float p) {
    p += __shfl_xor_sync(0xFFFFFFFFu, p, 1);
    p += __shfl_xor_sync(0xFFFFFFFFu, p, 2);
    p += __shfl_xor_sync(0xFFFFFFFFu, p, 4);
    return p;
}

__global__ __launch_bounds__(256) void k_agg(const float* __restrict__ XL,
                                             const float* __restrict__ XR,
                                             const float* __restrict__ att,
                                             const float* __restrict__ bias,
                                             float* __restrict__ out) {
    int warp = (blockIdx.x * blockDim.x + threadIdx.x) >> 5;
    int lane = threadIdx.x & 31;
    if (warp >= N_NODES) return;

    float4 a4 = __ldg((const float4*)att + lane);
    float4 xr = __ldg((const float4*)(XR + (size_t)warp * 128) + lane);
    int e0 = g_ROWPTR[warp];
    int e1 = g_ROWPTR[warp + 1];

    float m = -1e30f, s = 0.f;
    float4 acc = make_float4(0.f, 0.f, 0.f, 0.f);

    int e = e0;
    for (; e + 4 <= e1; e += 4) {
        int s0 = g_CSR[e], s1 = g_CSR[e + 1], s2 = g_CSR[e + 2], s3 = g_CSR[e + 3];
        float4 x0 = __ldg((const float4*)(XL + (size_t)s0 * 128) + lane);
        float4 x1 = __ldg((const float4*)(XL + (size_t)s1 * 128) + lane);
        float4 x2 = __ldg((const float4*)(XL + (size_t)s2 * 128) + lane);
        float4 x3 = __ldg((const float4*)(XL + (size_t)s3 * 128) + lane);

        float p0 = head_reduce(edge_logit(x0, xr, a4));
        float p1 = head_reduce(edge_logit(x1, xr, a4));
        float p2 = head_reduce(edge_logit(x2, xr, a4));
        float p3 = head_reduce(edge_logit(x3, xr, a4));

        float mn = fmaxf(m, fmaxf(fmaxf(p0, p1), fmaxf(p2, p3)));
        float c  = __expf(m - mn);
        float w0 = __expf(p0 - mn), w1 = __expf(p1 - mn);
        float w2 = __expf(p2 - mn), w3 = __expf(p3 - mn);
        s = s * c + w0 + w1 + w2 + w3;
        acc.x = acc.x * c + w0 * x0.x + w1 * x1.x + w2 * x2.x + w3 * x3.x;
        acc.y = acc.y * c + w0 * x0.y + w1 * x1.y + w2 * x2.y + w3 * x3.y;
        acc.z = acc.z * c + w0 * x0.z + w1 * x1.z + w2 * x2.z + w3 * x3.z;
        acc.w = acc.w * c + w0 * x0.w + w1 * x1.w + w2 * x2.w + w3 * x3.w;
        m = mn;
    }
    for (; e < e1; e++) {
        int src = g_CSR[e];
        float4 xs = __ldg((const float4*)(XL + (size_t)src * 128) + lane);
        float p = head_reduce(edge_logit(xs, xr, a4));
        float mn = fmaxf(m, p);
        float c  = __expf(m - mn);
        float w  = __expf(p - mn);
        s = s * c + w;
        acc.x = acc.x * c + w * xs.x;
        acc.y = acc.y * c + w * xs.y;
        acc.z = acc.z * c + w * xs.z;
        acc.w = acc.w * c + w * xs.w;
        m = mn;
    }

    float inv = 1.f / (s + 1e-16f);
    float4 b4 = __ldg((const float4*)bias + lane);
    float4 o;
    o.x = fmaxf(acc.x * inv + b4.x, 0.f);
    o.y = fmaxf(acc.y * inv + b4.y, 0.f);
    o.z = fmaxf(acc.z * inv + b4.z, 0.f);
    o.w = fmaxf(acc.w * inv + b4.w, 0.f);
    *((float4*)(out + (size_t)warp * 128) + lane) = o;
}

// ------------------------- launch --------------------------------------------
extern "C" void kernel_launch(void* const* d_in, const int* in_sizes, int n_in,
                              void* d_out, int out_size) {
    const float* x    = (const float*)d_in[0];
    const void*  ei   = d_in[1];
    const float* W1l  = (const float*)d_in[2];
    const float* W1r  = (const float*)d_in[3];
    const float* att1 = (const float*)d_in[4];
    const float* b1   = (const float*)d_in[5];
    const float* W2l  = (const float*)d_in[6];
    const float* W2r  = (const float*)d_in[7];
    const float* att2 = (const float*)d_in[8];
    const float* b2   = (const float*)d_in[9];
    float* out = (float*)d_out;

    float *XL, *XR, *H1;
    cudaGetSymbolAddress((void**)&XL, g_XL);
    cudaGetSymbolAddress((void**)&XR, g_XR);
    cudaGetSymbolAddress((void**)&H1, g_H1);

    cudaFuncSetAttribute(k_gemm_tc, cudaFuncAttributeMaxDynamicSharedMemorySize,
                         GEMM_SMEM_BYTES);

    // CSR build
    k_detect<<<1, 256>>>((const int*)ei);
    k_zero_deg<<<(N_NODES + 255) / 256, 256>>>();
    k_hist<<<(E_TOT + 255) / 256, 256>>>(ei);
    int nblk = (N_NODES + 1023) / 1024;
    k_scan1<<<nblk, 1024>>>();
    k_scan2<<<1, 32>>>(nblk);
    k_scan3<<<nblk, 1024>>>();
    k_scatter<<<(E_TOT + 255) / 256, 256>>>(ei);

    int gemm_grid = (N_NODES + 127) / 128;
    int agg_grid  = (N_NODES * 32 + 255) / 256;

    // layer 1
    k_gemm_tc<<<gemm_grid, 512, GEMM_SMEM_BYTES>>>(x, W1l, W1r, XL, XR, N_NODES);
    k_agg<<<agg_grid, 256>>>(XL, XR, att1, b1, H1);

    // layer 2
    k_gemm_tc<<<gemm_grid, 512, GEMM_SMEM_BYTES>>>(H1, W2l, W2r, XL, XR, N_NODES);
    k_agg<<<agg_grid, 256>>>(XL, XR, att2, b2, out);
}